// round 6
// baseline (speedup 1.0000x reference)
#include <cuda_runtime.h>
#include <stdint.h>

// ---------------------------------------------------------------------------
// DynamicFixedQuantizer: bit-exact JAX threefry stochastic rounding quantizer.
//
// Phase 1: zero counters.
// Phase 2: count overflow/underflow vs sigma0=0.25 thresholds (memory bound).
// Phase 3: derive sigma (faithful fp32 replication of _rescale), generate
//          r = jax.random.uniform(fold_in(key(42),0)) bit-exactly
//          (threefry-partitionable layout: bits[i] = y0^y1 of
//           threefry2x32(key, (0, i))), quantize, clip, store.
// ---------------------------------------------------------------------------

__device__ unsigned int g_over_cnt;
__device__ unsigned int g_under_cnt;

#define TF_ROUND(x0, x1, r)                          \
    {                                                \
        x0 += x1;                                    \
        x1 = __funnelshift_l(x1, x1, r);             \
        x1 ^= x0;                                    \
    }

// Full 20-round JAX threefry2x32 with input (x0=0, x1=c); returns y0 ^ y1
// (the partitionable 32-bit random-bits reduction).
__device__ __forceinline__ uint32_t tf_bits(uint32_t k0, uint32_t k1,
                                            uint32_t k2, uint32_t c)
{
    uint32_t x0 = k0;        // 0 + ks[0]
    uint32_t x1 = c + k1;    // c + ks[1]
    TF_ROUND(x0, x1, 13) TF_ROUND(x0, x1, 15) TF_ROUND(x0, x1, 26) TF_ROUND(x0, x1, 6)
    x0 += k1; x1 += k2 + 1u;
    TF_ROUND(x0, x1, 17) TF_ROUND(x0, x1, 29) TF_ROUND(x0, x1, 16) TF_ROUND(x0, x1, 24)
    x0 += k2; x1 += k0 + 2u;
    TF_ROUND(x0, x1, 13) TF_ROUND(x0, x1, 15) TF_ROUND(x0, x1, 26) TF_ROUND(x0, x1, 6)
    x0 += k0; x1 += k1 + 3u;
    TF_ROUND(x0, x1, 17) TF_ROUND(x0, x1, 29) TF_ROUND(x0, x1, 16) TF_ROUND(x0, x1, 24)
    x0 += k1; x1 += k2 + 4u;
    TF_ROUND(x0, x1, 13) TF_ROUND(x0, x1, 15) TF_ROUND(x0, x1, 26) TF_ROUND(x0, x1, 6)
    x0 += k2; x1 += k0 + 5u;
    return x0 ^ x1;
}

__global__ void k_init()
{
    g_over_cnt = 0u;
    g_under_cnt = 0u;
}

__global__ void __launch_bounds__(256) k_count(const float* __restrict__ x, int n)
{
    // sigma0 = 0.25, bit = 8, half = 128  (all exact fp32 constants)
    const float sigma = 0.25f;
    const float tmax = sigma * 128.0f - sigma;  // 31.75
    const float tmin = -sigma * 128.0f;         // -32
    const float hmax = 0.5f * tmax;             // 15.875
    const float hmin = 0.5f * tmin;             // -16

    unsigned int ov = 0u, un = 0u;
    const int n4 = n >> 2;
    const int tid = blockIdx.x * blockDim.x + threadIdx.x;
    const int stride = gridDim.x * blockDim.x;
    const float4* __restrict__ x4 = reinterpret_cast<const float4*>(x);

    for (int i = tid; i < n4; i += stride) {
        float4 v = x4[i];
        ov += (unsigned)(v.x > tmax) + (unsigned)(v.x < tmin)
            + (unsigned)(v.y > tmax) + (unsigned)(v.y < tmin)
            + (unsigned)(v.z > tmax) + (unsigned)(v.z < tmin)
            + (unsigned)(v.w > tmax) + (unsigned)(v.w < tmin);
        un += (unsigned)(v.x > hmax) + (unsigned)(v.x < hmin)
            + (unsigned)(v.y > hmax) + (unsigned)(v.y < hmin)
            + (unsigned)(v.z > hmax) + (unsigned)(v.z < hmin)
            + (unsigned)(v.w > hmax) + (unsigned)(v.w < hmin);
    }
    // scalar tail (n not multiple of 4)
    for (int i = (n4 << 2) + tid; i < n; i += stride) {
        float v = x[i];
        ov += (unsigned)(v > tmax) + (unsigned)(v < tmin);
        un += (unsigned)(v > hmax) + (unsigned)(v < hmin);
    }

    // warp butterfly reduction, one atomic per warp
    #pragma unroll
    for (int o = 16; o > 0; o >>= 1) {
        ov += __shfl_xor_sync(0xFFFFFFFFu, ov, o);
        un += __shfl_xor_sync(0xFFFFFFFFu, un, o);
    }
    if ((threadIdx.x & 31) == 0) {
        atomicAdd(&g_over_cnt, ov);
        atomicAdd(&g_under_cnt, un);
    }
}

__device__ __forceinline__ float quant_one(float v, uint32_t bits, float sigma,
                                           float inv_sigma, float tmin, float tmax)
{
    // JAX uniform[0,1): bitcast((bits >> 9) | 0x3f800000) - 1.0
    float u = __uint_as_float((bits >> 9) | 0x3f800000u) - 1.0f;
    // x/sigma is exact (sigma = power of 2) so fmaf == div-then-add, bit-exact
    float q = floorf(fmaf(v, inv_sigma, u));
    // jnp.clip: max then min
    return fminf(fmaxf(q * sigma, tmin), tmax);
}

__global__ void __launch_bounds__(256) k_quant(const float* __restrict__ x,
                                               float* __restrict__ out, int n,
                                               uint32_t k0, uint32_t k1)
{
    const uint32_t k2 = k0 ^ k1 ^ 0x1BD11BDAu;

    // Faithful _rescale sigma selection from counters
    float sigma = 0.25f;
    const float fn = __int2float_rn(n);
    const float over = __uint2float_rn(g_over_cnt) / fn;
    const float under = __uint2float_rn(g_under_cnt) / fn;
    if (over > 0.01f) {
        sigma = sigma * 2.0f;
    } else if (under < 0.01f) {
        sigma = sigma * 0.5f;
    }
    const float tmax = sigma * 128.0f - sigma;
    const float tmin = -sigma * 128.0f;
    const float inv_sigma = 1.0f / sigma;  // exact: sigma is a power of 2

    const uint32_t nthreads = gridDim.x * blockDim.x;
    const uint32_t tid = blockIdx.x * blockDim.x + threadIdx.x;
    const uint32_t stride4 = nthreads * 4u;
    const uint32_t nvec = (uint32_t)n & ~3u;

    for (uint32_t i = tid * 4u; i < nvec; i += stride4) {
        float4 v = *reinterpret_cast<const float4*>(x + i);
        // 4 independent ciphers -> ILP 4 to cover the 4-cyc ALU latency chain
        uint32_t b0 = tf_bits(k0, k1, k2, i);
        uint32_t b1 = tf_bits(k0, k1, k2, i + 1u);
        uint32_t b2 = tf_bits(k0, k1, k2, i + 2u);
        uint32_t b3 = tf_bits(k0, k1, k2, i + 3u);
        float4 o;
        o.x = quant_one(v.x, b0, sigma, inv_sigma, tmin, tmax);
        o.y = quant_one(v.y, b1, sigma, inv_sigma, tmin, tmax);
        o.z = quant_one(v.z, b2, sigma, inv_sigma, tmin, tmax);
        o.w = quant_one(v.w, b3, sigma, inv_sigma, tmin, tmax);
        *reinterpret_cast<float4*>(out + i) = o;
    }
    // scalar tail
    for (uint32_t i = nvec + tid; i < (uint32_t)n; i += nthreads) {
        uint32_t b = tf_bits(k0, k1, k2, i);
        out[i] = quant_one(x[i], b, sigma, inv_sigma, tmin, tmax);
    }
}

// ---------------------------------------------------------------------------
// Host-side threefry (identical 20-round cipher) to derive the folded key:
// key(42) = [0, 42]; fold_in(key, 0) = threefry2x32([0,42], [0,0]).
// ---------------------------------------------------------------------------
static inline uint32_t h_rotl(uint32_t v, int s)
{
    return (v << s) | (v >> (32 - s));
}

static void h_threefry(uint32_t k0, uint32_t k1, uint32_t& x0, uint32_t& x1)
{
    const uint32_t k2 = k0 ^ k1 ^ 0x1BD11BDAu;
    x0 += k0; x1 += k1;
    const int rots[5][4] = {{13, 15, 26, 6}, {17, 29, 16, 24}, {13, 15, 26, 6},
                            {17, 29, 16, 24}, {13, 15, 26, 6}};
    const uint32_t ks[3] = {k0, k1, k2};
    for (int g = 0; g < 5; g++) {
        for (int r = 0; r < 4; r++) {
            x0 += x1;
            x1 = h_rotl(x1, rots[g][r]);
            x1 ^= x0;
        }
        x0 += ks[(g + 1) % 3];
        x1 += ks[(g + 2) % 3] + (uint32_t)(g + 1);
    }
}

extern "C" void kernel_launch(void* const* d_in, const int* in_sizes, int n_in,
                              void* d_out, int out_size)
{
    const float* x = (const float*)d_in[0];
    float* out = (float*)d_out;
    const int n = in_sizes[0];

    // folded key = threefry2x32(key=[0,42], count=[0,0])
    uint32_t f0 = 0u, f1 = 0u;
    h_threefry(0u, 42u, f0, f1);

    k_init<<<1, 1>>>();
    k_count<<<1184, 256>>>(x, n);
    k_quant<<<4736, 256>>>(x, out, n, f0, f1);
}

// round 17
// speedup vs baseline: 1.1335x; 1.1335x over previous
#include <cuda_runtime.h>
#include <stdint.h>

// ---------------------------------------------------------------------------
// DynamicFixedQuantizer, speculate-and-verify single-pass version.
//
// k_main : quantize with speculated sigma=0.125 AND count overflow/underflow
//          (vs sigma0=0.25 thresholds) from the same loaded values.
//          Per-block partial counts -> slots (unconditional write, no init).
// k_reduce: 1 block reduces partials, runs the faithful _rescale decision,
//          publishes sigma.
// k_fix  : early-exit if speculation was right (sigma==0.125), else full
//          requantize with the true sigma (correct for any input).
// k_nop x2: padding so ncu -s 5 -c 1 profiles k_main next round.
//
// RNG is bit-exact JAX partitionable threefry2x32: bits[i] = y0^y1 of
// threefry2x32(fold_in(key(42),0), (0,i)); uniform = (bits>>9)*2^-23,
// proven identical to bitcast((bits>>9)|0x3f800000)-1.
// ---------------------------------------------------------------------------

#define GRID_MAIN 4736
#define TPB 256

__device__ unsigned int g_part_ov[GRID_MAIN];
__device__ unsigned int g_part_un[GRID_MAIN];
__device__ unsigned int g_sigma_bits;

#define TF_ROUND(x0, x1, r)                          \
    {                                                \
        x0 += x1;                                    \
        x1 = __funnelshift_l(x1, x1, r);             \
        x1 ^= x0;                                    \
    }

__device__ __forceinline__ uint32_t tf_bits(uint32_t k0, uint32_t k1,
                                            uint32_t k2, uint32_t c)
{
    uint32_t x0 = k0;        // 0 + ks[0]
    uint32_t x1 = c + k1;    // c + ks[1]
    TF_ROUND(x0, x1, 13) TF_ROUND(x0, x1, 15) TF_ROUND(x0, x1, 26) TF_ROUND(x0, x1, 6)
    x0 += k1; x1 += k2 + 1u;
    TF_ROUND(x0, x1, 17) TF_ROUND(x0, x1, 29) TF_ROUND(x0, x1, 16) TF_ROUND(x0, x1, 24)
    x0 += k2; x1 += k0 + 2u;
    TF_ROUND(x0, x1, 13) TF_ROUND(x0, x1, 15) TF_ROUND(x0, x1, 26) TF_ROUND(x0, x1, 6)
    x0 += k0; x1 += k1 + 3u;
    TF_ROUND(x0, x1, 17) TF_ROUND(x0, x1, 29) TF_ROUND(x0, x1, 16) TF_ROUND(x0, x1, 24)
    x0 += k1; x1 += k2 + 4u;
    TF_ROUND(x0, x1, 13) TF_ROUND(x0, x1, 15) TF_ROUND(x0, x1, 26) TF_ROUND(x0, x1, 6)
    x0 += k2; x1 += k0 + 5u;
    return x0 ^ x1;
}

// Bit-exact quantize: u = (bits>>9)*2^-23 (== bitcast trick, both exact);
// xs = v*inv_sigma exact (power-of-2 sigma); single-rounded add via fma;
// floor; *sigma exact-op-identical; clip max-then-min as jnp.clip.
__device__ __forceinline__ float quant_one(float v, uint32_t bits,
                                           float sigma, float inv_sigma,
                                           float tmin, float tmax)
{
    float u = __uint2float_rn(bits >> 9);           // exact, < 2^23
    float q = floorf(fmaf(u, 0x1p-23f, v * inv_sigma));
    return fminf(fmaxf(q * sigma, tmin), tmax);
}

// ---------------------------------------------------------------------------
// k_main: speculative quantize (sigma=0.125) + count in one pass
// ---------------------------------------------------------------------------
__global__ void __launch_bounds__(TPB) k_main(const float* __restrict__ x,
                                              float* __restrict__ out, int n,
                                              uint32_t k0, uint32_t k1)
{
    const uint32_t k2 = k0 ^ k1 ^ 0x1BD11BDAu;

    // _rescale thresholds at sigma0 = 0.25 (exact fp32 constants)
    const float T0MAX = 31.75f,  T0MIN = -32.0f;   // overflow bounds
    const float H0MAX = 15.875f, H0MIN = -16.0f;   // underflow (half) bounds

    // speculated sigma = 0.125
    const float SSIG = 0.125f, SINV = 8.0f;
    const float STMAX = 0.125f * 128.0f - 0.125f;  // 15.875
    const float STMIN = -0.125f * 128.0f;          // -16

    unsigned int ov = 0u, un = 0u;

    const uint32_t nthreads = gridDim.x * blockDim.x;
    const uint32_t tid = blockIdx.x * blockDim.x + threadIdx.x;
    const uint32_t stride4 = nthreads * 4u;
    const uint32_t nvec = (uint32_t)n & ~3u;

    for (uint32_t i = tid * 4u; i < nvec; i += stride4) {
        float4 v = *reinterpret_cast<const float4*>(x + i);

        // counts vs sigma0 thresholds (sum == OR since tmin < tmax)
        ov += (unsigned)(v.x > T0MAX) + (unsigned)(v.x < T0MIN)
            + (unsigned)(v.y > T0MAX) + (unsigned)(v.y < T0MIN)
            + (unsigned)(v.z > T0MAX) + (unsigned)(v.z < T0MIN)
            + (unsigned)(v.w > T0MAX) + (unsigned)(v.w < T0MIN);
        un += (unsigned)(v.x > H0MAX) + (unsigned)(v.x < H0MIN)
            + (unsigned)(v.y > H0MAX) + (unsigned)(v.y < H0MIN)
            + (unsigned)(v.z > H0MAX) + (unsigned)(v.z < H0MIN)
            + (unsigned)(v.w > H0MAX) + (unsigned)(v.w < H0MIN);

        // 4 independent ciphers -> ILP 4 covers the lat-4 ALU chains
        uint32_t b0 = tf_bits(k0, k1, k2, i);
        uint32_t b1 = tf_bits(k0, k1, k2, i + 1u);
        uint32_t b2 = tf_bits(k0, k1, k2, i + 2u);
        uint32_t b3 = tf_bits(k0, k1, k2, i + 3u);

        float4 o;
        o.x = quant_one(v.x, b0, SSIG, SINV, STMIN, STMAX);
        o.y = quant_one(v.y, b1, SSIG, SINV, STMIN, STMAX);
        o.z = quant_one(v.z, b2, SSIG, SINV, STMIN, STMAX);
        o.w = quant_one(v.w, b3, SSIG, SINV, STMIN, STMAX);
        *reinterpret_cast<float4*>(out + i) = o;
    }
    // scalar tail (n not multiple of 4)
    for (uint32_t i = nvec + tid; i < (uint32_t)n; i += nthreads) {
        float v = x[i];
        ov += (unsigned)(v > T0MAX) + (unsigned)(v < T0MIN);
        un += (unsigned)(v > H0MAX) + (unsigned)(v < H0MIN);
        uint32_t b = tf_bits(k0, k1, k2, i);
        out[i] = quant_one(v, b, SSIG, SINV, STMIN, STMAX);
    }

    // block reduction -> per-block slot (unconditional write each replay)
    #pragma unroll
    for (int o = 16; o > 0; o >>= 1) {
        ov += __shfl_xor_sync(0xFFFFFFFFu, ov, o);
        un += __shfl_xor_sync(0xFFFFFFFFu, un, o);
    }
    __shared__ unsigned int s_ov[TPB / 32];
    __shared__ unsigned int s_un[TPB / 32];
    const int wid = threadIdx.x >> 5;
    if ((threadIdx.x & 31) == 0) { s_ov[wid] = ov; s_un[wid] = un; }
    __syncthreads();
    if (threadIdx.x == 0) {
        unsigned int tov = 0u, tun = 0u;
        #pragma unroll
        for (int w = 0; w < TPB / 32; w++) { tov += s_ov[w]; tun += s_un[w]; }
        g_part_ov[blockIdx.x] = tov;
        g_part_un[blockIdx.x] = tun;
    }
}

// ---------------------------------------------------------------------------
// k_reduce: 1 block, faithful _rescale decision -> g_sigma_bits
// ---------------------------------------------------------------------------
__global__ void __launch_bounds__(1024) k_reduce(int n)
{
    unsigned int ov = 0u, un = 0u;
    for (int i = threadIdx.x; i < GRID_MAIN; i += 1024) {
        ov += g_part_ov[i];
        un += g_part_un[i];
    }
    #pragma unroll
    for (int o = 16; o > 0; o >>= 1) {
        ov += __shfl_xor_sync(0xFFFFFFFFu, ov, o);
        un += __shfl_xor_sync(0xFFFFFFFFu, un, o);
    }
    __shared__ unsigned int s_ov[32];
    __shared__ unsigned int s_un[32];
    const int wid = threadIdx.x >> 5;
    if ((threadIdx.x & 31) == 0) { s_ov[wid] = ov; s_un[wid] = un; }
    __syncthreads();
    if (threadIdx.x == 0) {
        unsigned int tov = 0u, tun = 0u;
        #pragma unroll
        for (int w = 0; w < 32; w++) { tov += s_ov[w]; tun += s_un[w]; }
        // faithful _rescale: doubles on overflow, halves on underflow
        float sigma = 0.25f;
        const float fn = __int2float_rn(n);
        const float over  = __uint2float_rn(tov) / fn;
        const float under = __uint2float_rn(tun) / fn;
        if (over > 0.01f) {
            sigma = sigma * 2.0f;
        } else if (under < 0.01f) {
            sigma = sigma * 0.5f;
        }
        g_sigma_bits = __float_as_uint(sigma);
    }
}

// ---------------------------------------------------------------------------
// k_fix: early-exit if speculation held, else full requantize with true sigma
// ---------------------------------------------------------------------------
__global__ void __launch_bounds__(TPB) k_fix(const float* __restrict__ x,
                                             float* __restrict__ out, int n,
                                             uint32_t k0, uint32_t k1)
{
    const float sigma = __uint_as_float(g_sigma_bits);
    if (sigma == 0.125f) return;   // speculation correct -> output already right

    const uint32_t k2 = k0 ^ k1 ^ 0x1BD11BDAu;
    const float tmax = sigma * 128.0f - sigma;
    const float tmin = -sigma * 128.0f;
    const float inv_sigma = 1.0f / sigma;  // exact: sigma is a power of 2

    const uint32_t nthreads = gridDim.x * blockDim.x;
    const uint32_t tid = blockIdx.x * blockDim.x + threadIdx.x;
    const uint32_t stride4 = nthreads * 4u;
    const uint32_t nvec = (uint32_t)n & ~3u;

    for (uint32_t i = tid * 4u; i < nvec; i += stride4) {
        float4 v = *reinterpret_cast<const float4*>(x + i);
        uint32_t b0 = tf_bits(k0, k1, k2, i);
        uint32_t b1 = tf_bits(k0, k1, k2, i + 1u);
        uint32_t b2 = tf_bits(k0, k1, k2, i + 2u);
        uint32_t b3 = tf_bits(k0, k1, k2, i + 3u);
        float4 o;
        o.x = quant_one(v.x, b0, sigma, inv_sigma, tmin, tmax);
        o.y = quant_one(v.y, b1, sigma, inv_sigma, tmin, tmax);
        o.z = quant_one(v.z, b2, sigma, inv_sigma, tmin, tmax);
        o.w = quant_one(v.w, b3, sigma, inv_sigma, tmin, tmax);
        *reinterpret_cast<float4*>(out + i) = o;
    }
    for (uint32_t i = nvec + tid; i < (uint32_t)n; i += nthreads) {
        uint32_t b = tf_bits(k0, k1, k2, i);
        out[i] = quant_one(x[i], b, sigma, inv_sigma, tmin, tmax);
    }
}

// Padding kernels: keep 5 launches per call so ncu's fixed "-s 5 -c 1"
// lands on the SECOND call's k_main (launch index 5) next profile.
__global__ void k_nop() {}

// ---------------------------------------------------------------------------
// Host-side threefry for the folded key: fold_in(key(42),0)
// ---------------------------------------------------------------------------
static inline uint32_t h_rotl(uint32_t v, int s)
{
    return (v << s) | (v >> (32 - s));
}

static void h_threefry(uint32_t k0, uint32_t k1, uint32_t& x0, uint32_t& x1)
{
    const uint32_t k2 = k0 ^ k1 ^ 0x1BD11BDAu;
    x0 += k0; x1 += k1;
    const int rots[5][4] = {{13, 15, 26, 6}, {17, 29, 16, 24}, {13, 15, 26, 6},
                            {17, 29, 16, 24}, {13, 15, 26, 6}};
    const uint32_t ks[3] = {k0, k1, k2};
    for (int g = 0; g < 5; g++) {
        for (int r = 0; r < 4; r++) {
            x0 += x1;
            x1 = h_rotl(x1, rots[g][r]);
            x1 ^= x0;
        }
        x0 += ks[(g + 1) % 3];
        x1 += ks[(g + 2) % 3] + (uint32_t)(g + 1);
    }
}

extern "C" void kernel_launch(void* const* d_in, const int* in_sizes, int n_in,
                              void* d_out, int out_size)
{
    const float* x = (const float*)d_in[0];
    float* out = (float*)d_out;
    const int n = in_sizes[0];

    uint32_t f0 = 0u, f1 = 0u;
    h_threefry(0u, 42u, f0, f1);

    k_main<<<GRID_MAIN, TPB>>>(x, out, n, f0, f1);
    k_reduce<<<1, 1024>>>(n);
    k_fix<<<GRID_MAIN, TPB>>>(x, out, n, f0, f1);
    k_nop<<<1, 1>>>();
    k_nop<<<1, 1>>>();
}